// round 3
// baseline (speedup 1.0000x reference)
#include <cuda_runtime.h>
#include <math.h>

#define BDIM 4096
#define DDIM 1024
#define NCOLBLK 32   // 4096 / 128
#define SCALE 20.0f

// Scratch (allocation-free per harness rules)
__device__ float g_inv_a[BDIM];
__device__ float g_inv_p[BDIM];
__device__ float g_partial[BDIM * NCOLBLK];  // [row][colblock] partial sums of exp(s-20)
__device__ float g_diag[BDIM];               // s_ii

// ---------------------------------------------------------------------------
// 1) Row inverse norms: one block per row (A rows: 0..4095, P rows: 4096..8191)
// ---------------------------------------------------------------------------
__global__ void norm_kernel(const float* __restrict__ A, const float* __restrict__ P) {
    int row = blockIdx.x & (BDIM - 1);
    bool isA = blockIdx.x < BDIM;
    const float4* src = (const float4*)((isA ? A : P) + (size_t)row * DDIM);
    float4 v = src[threadIdx.x];           // 256 threads * 4 floats = 1024
    float s = v.x * v.x + v.y * v.y + v.z * v.z + v.w * v.w;
    #pragma unroll
    for (int o = 16; o > 0; o >>= 1) s += __shfl_down_sync(0xffffffffu, s, o);
    __shared__ float ws[8];
    if ((threadIdx.x & 31) == 0) ws[threadIdx.x >> 5] = s;
    __syncthreads();
    if (threadIdx.x == 0) {
        float t = 0.0f;
        #pragma unroll
        for (int i = 0; i < 8; i++) t += ws[i];
        float inv = 1.0f / fmaxf(sqrtf(t), 1e-8f);
        if (isA) g_inv_a[row] = inv; else g_inv_p[row] = inv;
    }
}

// ---------------------------------------------------------------------------
// 2) Fused normalized GEMM (128x128x16 tiles, 8x8 per thread) + exp-sum epilogue
//    grid = (32 colblocks, 32 rowblocks), block = 256 threads
// ---------------------------------------------------------------------------
__global__ __launch_bounds__(256) void gemm_lse_kernel(const float* __restrict__ A,
                                                       const float* __restrict__ P) {
    __shared__ float As[16][128];
    __shared__ float Bs[16][128];
    __shared__ float red[128][17];  // padded to dodge bank conflicts on read

    const int tid  = threadIdx.x;
    const int tx   = tid & 15;
    const int ty   = tid >> 4;
    const int brow = blockIdx.y;
    const int bcol = blockIdx.x;

    // Each thread loads 2 adjacent float4 (one 32B chunk) of one tile row per stage.
    const int ldrow = tid >> 1;           // 0..127
    const int ldc4  = (tid & 1) * 2;      // float4 index 0 or 2 within 16-wide k-slab
    const float ia = g_inv_a[brow * 128 + ldrow];
    const float ip = g_inv_p[bcol * 128 + ldrow];
    const float* Abase = A + (size_t)(brow * 128 + ldrow) * DDIM;
    const float* Pbase = P + (size_t)(bcol * 128 + ldrow) * DDIM;

    float acc[8][8];
    #pragma unroll
    for (int i = 0; i < 8; i++)
        #pragma unroll
        for (int j = 0; j < 8; j++) acc[i][j] = 0.0f;

    for (int k0 = 0; k0 < DDIM; k0 += 16) {
        #pragma unroll
        for (int l = 0; l < 2; l++) {
            int c4 = ldc4 + l;
            float4 va = *(const float4*)(Abase + k0 + c4 * 4);
            As[c4 * 4 + 0][ldrow] = va.x * ia;
            As[c4 * 4 + 1][ldrow] = va.y * ia;
            As[c4 * 4 + 2][ldrow] = va.z * ia;
            As[c4 * 4 + 3][ldrow] = va.w * ia;
            float4 vp = *(const float4*)(Pbase + k0 + c4 * 4);
            Bs[c4 * 4 + 0][ldrow] = vp.x * ip;
            Bs[c4 * 4 + 1][ldrow] = vp.y * ip;
            Bs[c4 * 4 + 2][ldrow] = vp.z * ip;
            Bs[c4 * 4 + 3][ldrow] = vp.w * ip;
        }
        __syncthreads();
        #pragma unroll
        for (int kk = 0; kk < 16; kk++) {
            float a[8], b[8];
            #pragma unroll
            for (int i = 0; i < 8; i++) a[i] = As[kk][ty * 8 + i];
            #pragma unroll
            for (int j = 0; j < 8; j++) b[j] = Bs[kk][tx * 8 + j];
            #pragma unroll
            for (int i = 0; i < 8; i++)
                #pragma unroll
                for (int j = 0; j < 8; j++) acc[i][j] += a[i] * b[j];
        }
        __syncthreads();
    }

    // Epilogue: scores -> exp(s - 20), per-row partial sums; capture diagonal.
    const int rowbase = brow * 128 + ty * 8;
    const int colbase = bcol * 128 + tx * 8;
    #pragma unroll
    for (int i = 0; i < 8; i++) {
        float rp = 0.0f;
        #pragma unroll
        for (int j = 0; j < 8; j++) {
            float s = SCALE * acc[i][j];
            rp += expf(s - SCALE);
            if (rowbase + i == colbase + j) g_diag[rowbase + i] = s;
        }
        red[ty * 8 + i][tx] = rp;
    }
    __syncthreads();
    if (tid < 128) {
        float s = 0.0f;
        #pragma unroll
        for (int c = 0; c < 16; c++) s += red[tid][c];
        g_partial[(size_t)(brow * 128 + tid) * NCOLBLK + bcol] = s;
    }
}

// ---------------------------------------------------------------------------
// 3) Finalize: loss = mean over rows of (log(sum partials) + 20 - diag)
//    Single block, fixed summation order -> deterministic.
// ---------------------------------------------------------------------------
__global__ void finalize_kernel(float* __restrict__ out) {
    __shared__ float sred[256];
    float local = 0.0f;
    for (int r = threadIdx.x; r < BDIM; r += 256) {
        float s = 0.0f;
        #pragma unroll
        for (int c = 0; c < NCOLBLK; c++) s += g_partial[(size_t)r * NCOLBLK + c];
        local += logf(s) + SCALE - g_diag[r];
    }
    sred[threadIdx.x] = local;
    __syncthreads();
    #pragma unroll
    for (int o = 128; o > 0; o >>= 1) {
        if (threadIdx.x < o) sred[threadIdx.x] += sred[threadIdx.x + o];
        __syncthreads();
    }
    if (threadIdx.x == 0) out[0] = sred[0] * (1.0f / (float)BDIM);
}

// ---------------------------------------------------------------------------
extern "C" void kernel_launch(void* const* d_in, const int* in_sizes, int n_in,
                              void* d_out, int out_size) {
    const float* A = (const float*)d_in[0];   // anchor_emb  [4096, 1024]
    const float* P = (const float*)d_in[1];   // pos_negs_emb[4096, 1024]
    float* out = (float*)d_out;

    norm_kernel<<<2 * BDIM, 256>>>(A, P);
    gemm_lse_kernel<<<dim3(NCOLBLK, BDIM / 128), 256>>>(A, P);
    finalize_kernel<<<1, 256>>>(out);
}

// round 5
// speedup vs baseline: 1.7318x; 1.7318x over previous
#include <cuda_runtime.h>
#include <cstdint>
#include <math.h>

#define BDIM 4096
#define DDIM 1024
#define TM 128
#define TN 128
#define NBLK (BDIM / TM)      // 32 row/col blocks
#define NS 3                  // cp.async pipeline stages
#define KC 32                 // k-floats per chunk
#define NCHUNK (DDIM / KC)    // 32
#define APAD 36               // padded floats per smem row (conflict-free frags)
#define TILE_F (TM * APAD)    // 4608 floats per tile
#define STAGE_F (2 * TILE_F)  // A + B tile per stage
#define SCALE 20.0f

// Scratch (allocation-free per harness rules)
__device__ float g_inv_a[BDIM];
__device__ float g_inv_p[BDIM];
__device__ float g_partial[BDIM * NBLK];
__device__ float g_diag[BDIM];

// ---------------------------------------------------------------- helpers
__device__ __forceinline__ uint32_t smem_u32(const void* p) {
    uint32_t a;
    asm("{ .reg .u64 t; cvta.to.shared.u64 t, %1; cvt.u32.u64 %0, t; }" : "=r"(a) : "l"(p));
    return a;
}
__device__ __forceinline__ void cp_async16(uint32_t dst, const void* src) {
    asm volatile("cp.async.cg.shared.global [%0], [%1], 16;" :: "r"(dst), "l"(src));
}
#define CP_COMMIT() asm volatile("cp.async.commit_group;" ::: "memory")
template <int N>
__device__ __forceinline__ void cp_wait() {
    asm volatile("cp.async.wait_group %0;" :: "n"(N) : "memory");
}
// Legacy tf32 tensor-core MMA: base-target PTX (sm_80+), no 'a'-arch needed.
__device__ __forceinline__ void mma_tf32(float* d, const uint32_t* a, const uint32_t* b) {
    asm volatile(
        "mma.sync.aligned.m16n8k8.row.col.f32.tf32.tf32.f32 "
        "{%0,%1,%2,%3}, {%4,%5,%6,%7}, {%8,%9}, {%0,%1,%2,%3};"
        : "+f"(d[0]), "+f"(d[1]), "+f"(d[2]), "+f"(d[3])
        : "r"(a[0]), "r"(a[1]), "r"(a[2]), "r"(a[3]), "r"(b[0]), "r"(b[1]));
}

// ---------------------------------------------------------------------------
// 1) Row inverse norms
// ---------------------------------------------------------------------------
__global__ void norm_kernel(const float* __restrict__ A, const float* __restrict__ P) {
    int row = blockIdx.x & (BDIM - 1);
    bool isA = blockIdx.x < BDIM;
    const float4* src = (const float4*)((isA ? A : P) + (size_t)row * DDIM);
    float4 v = src[threadIdx.x];
    float s = v.x * v.x + v.y * v.y + v.z * v.z + v.w * v.w;
    #pragma unroll
    for (int o = 16; o > 0; o >>= 1) s += __shfl_down_sync(0xffffffffu, s, o);
    __shared__ float ws[8];
    if ((threadIdx.x & 31) == 0) ws[threadIdx.x >> 5] = s;
    __syncthreads();
    if (threadIdx.x == 0) {
        float t = 0.0f;
        #pragma unroll
        for (int i = 0; i < 8; i++) t += ws[i];
        float inv = 1.0f / fmaxf(sqrtf(t), 1e-8f);
        if (isA) g_inv_a[row] = inv; else g_inv_p[row] = inv;
    }
}

// ---------------------------------------------------------------------------
// 2) tf32 mma.sync GEMM (128x128 tile, 8 warps) + fused exp-sum epilogue
//    grid = (32, 32), block = 256
// ---------------------------------------------------------------------------
__device__ __forceinline__ void load_chunk(float* smf, int c, int tid,
                                           const float* Ab, const float* Pb) {
    float* st = smf + (c % NS) * STAGE_F;
    const int k0 = c * KC;
    // A tile: 128 rows x 32 floats -> 1024 16B quads; 256 threads, 4 iters
    #pragma unroll
    for (int j = 0; j < 4; j++) {
        int q = j * 256 + tid, row = q >> 3, quad = q & 7;
        cp_async16(smem_u32(st + row * APAD + quad * 4),
                   Ab + (size_t)row * DDIM + k0 + quad * 4);
    }
    // B tile: same shape
    float* stb = st + TILE_F;
    #pragma unroll
    for (int j = 0; j < 4; j++) {
        int q = j * 256 + tid, row = q >> 3, quad = q & 7;
        cp_async16(smem_u32(stb + row * APAD + quad * 4),
                   Pb + (size_t)row * DDIM + k0 + quad * 4);
    }
    CP_COMMIT();
}

__global__ __launch_bounds__(256, 1) void gemm_mma_kernel(const float* __restrict__ A,
                                                          const float* __restrict__ P) {
    extern __shared__ float smf[];
    __shared__ float s_ia[TM];       // 20 * inv_a for this row tile
    __shared__ float s_ip[TN];       // inv_p for this col tile
    __shared__ float red[TM][2];

    const int tid  = threadIdx.x;
    const int lane = tid & 31;
    const int wid  = tid >> 5;
    const int wm   = (wid & 3) * 32;   // warp row offset in tile
    const int wn   = (wid >> 2) * 64;  // warp col offset in tile
    const int brow = blockIdx.y, bcol = blockIdx.x;

    const float* Ab = A + (size_t)brow * TM * DDIM;
    const float* Pb = P + (size_t)bcol * TN * DDIM;

    if (tid < 128)       s_ia[tid]       = SCALE * g_inv_a[brow * TM + tid];
    else                 s_ip[tid - 128] = g_inv_p[bcol * TN + (tid - 128)];

    // Prologue: prefetch chunks 0,1
    load_chunk(smf, 0, tid, Ab, Pb);
    load_chunk(smf, 1, tid, Ab, Pb);

    float acc[2][8][4];
    #pragma unroll
    for (int mt = 0; mt < 2; mt++)
        #pragma unroll
        for (int nt = 0; nt < 8; nt++)
            #pragma unroll
            for (int r = 0; r < 4; r++) acc[mt][nt][r] = 0.0f;

    for (int c = 0; c < NCHUNK; c++) {
        if (c + 2 < NCHUNK) cp_wait<1>(); else cp_wait<0>();
        __syncthreads();   // publishes chunk c; also closes WAR on stage (c+2)%NS
        if (c + 2 < NCHUNK) load_chunk(smf, c + 2, tid, Ab, Pb);

        const float* sA = smf + (c % NS) * STAGE_F;
        const float* sB = sA + TILE_F;
        const int r0 = wm + (lane >> 2);

        #pragma unroll
        for (int kk = 0; kk < 4; kk++) {
            const int c0 = kk * 8 + (lane & 3);
            uint32_t a[2][4], b[8][2];
            #pragma unroll
            for (int mt = 0; mt < 2; mt++) {
                const float* p = sA + (r0 + mt * 16) * APAD + c0;
                a[mt][0] = __float_as_uint(p[0]);
                a[mt][1] = __float_as_uint(p[8 * APAD]);
                a[mt][2] = __float_as_uint(p[4]);
                a[mt][3] = __float_as_uint(p[8 * APAD + 4]);
            }
            #pragma unroll
            for (int nt = 0; nt < 8; nt++) {
                const float* p = sB + (wn + nt * 8 + (lane >> 2)) * APAD + c0;
                b[nt][0] = __float_as_uint(p[0]);
                b[nt][1] = __float_as_uint(p[4]);
            }
            #pragma unroll
            for (int mt = 0; mt < 2; mt++)
                #pragma unroll
                for (int nt = 0; nt < 8; nt++)
                    mma_tf32(acc[mt][nt], a[mt], b[nt]);
        }
    }
    __syncthreads();  // all compute done before epilogue reuses nothing, but keeps red[] safe

    // Epilogue: s = acc * (20*inv_a) * inv_p ; per-row sum of exp(s-20); diag capture.
    float rs[2][2] = {{0.0f, 0.0f}, {0.0f, 0.0f}};
    #pragma unroll
    for (int mt = 0; mt < 2; mt++) {
        #pragma unroll
        for (int h = 0; h < 2; h++) {
            const int rloc = wm + mt * 16 + (lane >> 2) + h * 8;
            const float ia = s_ia[rloc];
            const int grow = brow * TM + rloc;
            float acc_rs = 0.0f;
            #pragma unroll
            for (int nt = 0; nt < 8; nt++) {
                #pragma unroll
                for (int q = 0; q < 2; q++) {
                    const int cloc = wn + nt * 8 + (lane & 3) * 2 + q;
                    float s = acc[mt][nt][h * 2 + q] * ia * s_ip[cloc];
                    acc_rs += __expf(s - SCALE);
                    if (brow == bcol && rloc == cloc) g_diag[grow] = s;
                }
            }
            rs[mt][h] = acc_rs;
        }
    }
    // reduce across the 4 lanes sharing each row (lane&3 varies, lane>>2 fixed)
    #pragma unroll
    for (int mt = 0; mt < 2; mt++)
        #pragma unroll
        for (int h = 0; h < 2; h++) {
            rs[mt][h] += __shfl_xor_sync(0xffffffffu, rs[mt][h], 1);
            rs[mt][h] += __shfl_xor_sync(0xffffffffu, rs[mt][h], 2);
        }
    if ((lane & 3) == 0) {
        #pragma unroll
        for (int mt = 0; mt < 2; mt++)
            #pragma unroll
            for (int h = 0; h < 2; h++)
                red[wm + mt * 16 + (lane >> 2) + h * 8][wid >> 2] = rs[mt][h];
    }
    __syncthreads();
    if (tid < TM) {
        float t = red[tid][0] + red[tid][1];
        g_partial[(size_t)(brow * TM + tid) * NBLK + bcol] = t;
    }
}

// ---------------------------------------------------------------------------
// 3) Finalize: loss = mean over rows of (log(sum partials) + 20 - diag)
// ---------------------------------------------------------------------------
__global__ void finalize_kernel(float* __restrict__ out) {
    __shared__ float sred[256];
    float local = 0.0f;
    for (int r = threadIdx.x; r < BDIM; r += 256) {
        float s = 0.0f;
        #pragma unroll
        for (int c = 0; c < NBLK; c++) s += g_partial[(size_t)r * NBLK + c];
        local += logf(s) + SCALE - g_diag[r];
    }
    sred[threadIdx.x] = local;
    __syncthreads();
    #pragma unroll
    for (int o = 128; o > 0; o >>= 1) {
        if (threadIdx.x < o) sred[threadIdx.x] += sred[threadIdx.x + o];
        __syncthreads();
    }
    if (threadIdx.x == 0) out[0] = sred[0] * (1.0f / (float)BDIM);
}

// ---------------------------------------------------------------------------
extern "C" void kernel_launch(void* const* d_in, const int* in_sizes, int n_in,
                              void* d_out, int out_size) {
    const float* A = (const float*)d_in[0];   // anchor_emb  [4096, 1024]
    const float* P = (const float*)d_in[1];   // pos_negs_emb[4096, 1024]
    float* out = (float*)d_out;

    const int smem = NS * STAGE_F * sizeof(float);  // 110592 B
    cudaFuncSetAttribute(gemm_mma_kernel,
                         cudaFuncAttributeMaxDynamicSharedMemorySize, smem);

    norm_kernel<<<2 * BDIM, 256>>>(A, P);
    gemm_mma_kernel<<<dim3(NBLK, NBLK), 256, smem>>>(A, P);
    finalize_kernel<<<1, 256>>>(out);
}

// round 6
// speedup vs baseline: 4.2237x; 2.4388x over previous
#include <cuda_runtime.h>
#include <cuda_fp16.h>
#include <cstdint>
#include <math.h>

#define BDIM 4096
#define DDIM 1024
#define TM 128
#define TN 128
#define NBLK (BDIM / TM)      // 32 row/col blocks
#define NS 4                  // cp.async pipeline stages
#define KC 64                 // k-halfs per chunk
#define NCHUNK (DDIM / KC)    // 16
#define LDB 72                // padded halfs per smem row (144B: conflict-free LDSM)
#define TILE_H (TM * LDB)     // halfs per tile
#define STAGE_H (2 * TILE_H)  // A + B tile per stage
#define SCALE 20.0f

// Scratch (allocation-free per harness rules)
__device__ __half g_a16[BDIM * DDIM];   // fp16 copy of anchor
__device__ __half g_p16[BDIM * DDIM];   // fp16 copy of pos_negs
__device__ float g_inv_a[BDIM];
__device__ float g_inv_p[BDIM];
__device__ float g_partial[BDIM * NBLK];
__device__ float g_diag[BDIM];

// ---------------------------------------------------------------- helpers
__device__ __forceinline__ uint32_t smem_u32(const void* p) {
    uint32_t a;
    asm("{ .reg .u64 t; cvta.to.shared.u64 t, %1; cvt.u32.u64 %0, t; }" : "=r"(a) : "l"(p));
    return a;
}
__device__ __forceinline__ void cp_async16(uint32_t dst, const void* src) {
    asm volatile("cp.async.cg.shared.global [%0], [%1], 16;" :: "r"(dst), "l"(src));
}
#define CP_COMMIT() asm volatile("cp.async.commit_group;" ::: "memory")
template <int N>
__device__ __forceinline__ void cp_wait() {
    asm volatile("cp.async.wait_group %0;" :: "n"(N) : "memory");
}
__device__ __forceinline__ void ldsm_x4(uint32_t* r, uint32_t addr) {
    asm volatile("ldmatrix.sync.aligned.m8n8.x4.shared.b16 {%0,%1,%2,%3}, [%4];"
                 : "=r"(r[0]), "=r"(r[1]), "=r"(r[2]), "=r"(r[3]) : "r"(addr));
}
// fp16 tensor-core MMA with fp32 accumulate: base-target PTX (sm_80+).
__device__ __forceinline__ void mma_f16(float* d, const uint32_t* a, const uint32_t* b) {
    asm volatile(
        "mma.sync.aligned.m16n8k16.row.col.f32.f16.f16.f32 "
        "{%0,%1,%2,%3}, {%4,%5,%6,%7}, {%8,%9}, {%0,%1,%2,%3};"
        : "+f"(d[0]), "+f"(d[1]), "+f"(d[2]), "+f"(d[3])
        : "r"(a[0]), "r"(a[1]), "r"(a[2]), "r"(a[3]), "r"(b[0]), "r"(b[1]));
}

// ---------------------------------------------------------------------------
// 1) Row inverse norms + fp32->fp16 conversion. One warp per row, grid 1024.
// ---------------------------------------------------------------------------
__global__ void norm_kernel(const float* __restrict__ A, const float* __restrict__ P) {
    const int row  = (blockIdx.x & 511) * 8 + (threadIdx.x >> 5);
    const bool isA = blockIdx.x < 512;
    const int lane = threadIdx.x & 31;
    const float* src = (isA ? A : P) + (size_t)row * DDIM;
    __half* dst = (isA ? g_a16 : g_p16) + (size_t)row * DDIM;

    float s = 0.0f;
    float4 v[8];
    #pragma unroll
    for (int i = 0; i < 8; i++) {
        v[i] = ((const float4*)src)[i * 32 + lane];
        s += v[i].x * v[i].x + v[i].y * v[i].y + v[i].z * v[i].z + v[i].w * v[i].w;
    }
    #pragma unroll
    for (int i = 0; i < 8; i++) {
        __half2 h0 = __floats2half2_rn(v[i].x, v[i].y);
        __half2 h1 = __floats2half2_rn(v[i].z, v[i].w);
        ((__half2*)dst)[(i * 32 + lane) * 2 + 0] = h0;
        ((__half2*)dst)[(i * 32 + lane) * 2 + 1] = h1;
    }
    #pragma unroll
    for (int o = 16; o > 0; o >>= 1) s += __shfl_xor_sync(0xffffffffu, s, o);
    if (lane == 0) {
        float inv = 1.0f / fmaxf(sqrtf(s), 1e-8f);
        if (isA) g_inv_a[row] = inv; else g_inv_p[row] = inv;
    }
}

// ---------------------------------------------------------------------------
// 2) fp16 mma.sync GEMM (128x128 tile, 8 warps, ldmatrix) + fused exp-sum
//    grid = (32, 32), block = 256
// ---------------------------------------------------------------------------
__device__ __forceinline__ void load_chunk(__half* smh, int c, int tid,
                                           const __half* Ab, const __half* Pb) {
    __half* st = smh + (c % NS) * STAGE_H;
    const int k0 = c * KC;
    const int row = tid >> 3, quad = tid & 7;   // 32 rows per pass of 256 thr? no: 256/8=32... 
    // 128 rows x 8 quads = 1024 quads per tile; 256 threads -> 4 iters; same for B
    #pragma unroll
    for (int j = 0; j < 4; j++) {
        int r = j * 32 + row;
        cp_async16(smem_u32(st + r * LDB + quad * 8),
                   Ab + (size_t)r * DDIM + k0 + quad * 8);
    }
    __half* stb = st + TILE_H;
    #pragma unroll
    for (int j = 0; j < 4; j++) {
        int r = j * 32 + row;
        cp_async16(smem_u32(stb + r * LDB + quad * 8),
                   Pb + (size_t)r * DDIM + k0 + quad * 8);
    }
    CP_COMMIT();
}

__global__ __launch_bounds__(256, 1) void gemm_mma_kernel() {
    extern __shared__ __half smh[];
    __shared__ float s_ia[TM];
    __shared__ float s_ip[TN];
    __shared__ float red[TM][2];

    const int tid  = threadIdx.x;
    const int lane = tid & 31;
    const int wid  = tid >> 5;
    const int wm   = (wid & 3) * 32;   // warp row offset
    const int wn   = (wid >> 2) * 64;  // warp col offset
    const int brow = blockIdx.y, bcol = blockIdx.x;

    const __half* Ab = g_a16 + (size_t)brow * TM * DDIM;
    const __half* Pb = g_p16 + (size_t)bcol * TN * DDIM;

    if (tid < 128)       s_ia[tid]       = SCALE * g_inv_a[brow * TM + tid];
    else                 s_ip[tid - 128] = g_inv_p[bcol * TN + (tid - 128)];

    // Prologue: prefetch chunks 0..NS-2
    #pragma unroll
    for (int c = 0; c < NS - 1; c++) load_chunk(smh, c, tid, Ab, Pb);

    float acc[2][8][4];
    #pragma unroll
    for (int mt = 0; mt < 2; mt++)
        #pragma unroll
        for (int nt = 0; nt < 8; nt++)
            #pragma unroll
            for (int r = 0; r < 4; r++) acc[mt][nt][r] = 0.0f;

    // ldmatrix per-thread row addressing: tile = lane>>3, row-in-tile = lane&7
    const int lt = lane >> 3, lr = lane & 7;

    for (int c = 0; c < NCHUNK; c++) {
        if (c < NCHUNK - 3)      cp_wait<2>();
        else if (c == NCHUNK - 3) cp_wait<2>();
        else if (c == NCHUNK - 2) cp_wait<1>();
        else                      cp_wait<0>();
        __syncthreads();   // publish chunk c; closes WAR on stage (c+NS-1)%NS
        if (c + NS - 1 < NCHUNK) load_chunk(smh, c + NS - 1, tid, Ab, Pb);

        const __half* sA = smh + (c % NS) * STAGE_H;
        const __half* sB = sA + TILE_H;

        // Base LDSM addresses (bytes) for this chunk
        // A tiles for x4: (m+(lt&1)*8+lr, k+(lt>>1)*8)
        uint32_t aAddr[2], bAddr[4];
        #pragma unroll
        for (int mt = 0; mt < 2; mt++)
            aAddr[mt] = smem_u32(sA + (wm + mt * 16 + (lt & 1) * 8 + lr) * LDB + (lt >> 1) * 8);
        // B tiles for x4 over an nt-pair: (n+(lt>>1)*8+lr, k+(lt&1)*8)
        #pragma unroll
        for (int np = 0; np < 4; np++)
            bAddr[np] = smem_u32(sB + (wn + np * 16 + (lt >> 1) * 8 + lr) * LDB + (lt & 1) * 8);

        #pragma unroll
        for (int kk = 0; kk < 4; kk++) {           // 4 x k16 covers KC=64
            uint32_t a[2][4], bf[16];
            #pragma unroll
            for (int mt = 0; mt < 2; mt++) ldsm_x4(a[mt], aAddr[mt] + kk * 32);
            #pragma unroll
            for (int np = 0; np < 4; np++) ldsm_x4(&bf[np * 4], bAddr[np] + kk * 32);
            #pragma unroll
            for (int mt = 0; mt < 2; mt++)
                #pragma unroll
                for (int nt = 0; nt < 8; nt++)
                    mma_f16(acc[mt][nt], a[mt], &bf[nt * 2]);
        }
    }
    __syncthreads();

    // Epilogue: s = acc * (20*inv_a) * inv_p ; per-row sum of exp(s-20); diag.
    float rs[2][2] = {{0.0f, 0.0f}, {0.0f, 0.0f}};
    #pragma unroll
    for (int mt = 0; mt < 2; mt++) {
        #pragma unroll
        for (int h = 0; h < 2; h++) {
            const int rloc = wm + mt * 16 + (lane >> 2) + h * 8;
            const float ia = s_ia[rloc];
            const int grow = brow * TM + rloc;
            float acc_rs = 0.0f;
            #pragma unroll
            for (int nt = 0; nt < 8; nt++) {
                #pragma unroll
                for (int q = 0; q < 2; q++) {
                    const int cloc = wn + nt * 8 + (lane & 3) * 2 + q;
                    float s = acc[mt][nt][h * 2 + q] * ia * s_ip[cloc];
                    acc_rs += __expf(s - SCALE);
                    if (brow == bcol && rloc == cloc) g_diag[grow] = s;
                }
            }
            rs[mt][h] = acc_rs;
        }
    }
    #pragma unroll
    for (int mt = 0; mt < 2; mt++)
        #pragma unroll
        for (int h = 0; h < 2; h++) {
            rs[mt][h] += __shfl_xor_sync(0xffffffffu, rs[mt][h], 1);
            rs[mt][h] += __shfl_xor_sync(0xffffffffu, rs[mt][h], 2);
        }
    if ((lane & 3) == 0) {
        #pragma unroll
        for (int mt = 0; mt < 2; mt++)
            #pragma unroll
            for (int h = 0; h < 2; h++)
                red[wm + mt * 16 + (lane >> 2) + h * 8][wid >> 2] = rs[mt][h];
    }
    __syncthreads();
    if (tid < TM) {
        float t = red[tid][0] + red[tid][1];
        g_partial[(size_t)(brow * TM + tid) * NBLK + bcol] = t;
    }
}

// ---------------------------------------------------------------------------
// 3) Finalize: loss = mean over rows of (log(sum partials) + 20 - diag)
// ---------------------------------------------------------------------------
__global__ void finalize_kernel(float* __restrict__ out) {
    __shared__ float sred[256];
    float local = 0.0f;
    for (int r = threadIdx.x; r < BDIM; r += 256) {
        float s = 0.0f;
        #pragma unroll
        for (int c = 0; c < NBLK; c++) s += g_partial[(size_t)r * NBLK + c];
        local += logf(s) + SCALE - g_diag[r];
    }
    sred[threadIdx.x] = local;
    __syncthreads();
    #pragma unroll
    for (int o = 128; o > 0; o >>= 1) {
        if (threadIdx.x < o) sred[threadIdx.x] += sred[threadIdx.x + o];
        __syncthreads();
    }
    if (threadIdx.x == 0) out[0] = sred[0] * (1.0f / (float)BDIM);
}

// ---------------------------------------------------------------------------
extern "C" void kernel_launch(void* const* d_in, const int* in_sizes, int n_in,
                              void* d_out, int out_size) {
    const float* A = (const float*)d_in[0];   // anchor_emb  [4096, 1024]
    const float* P = (const float*)d_in[1];   // pos_negs_emb[4096, 1024]
    float* out = (float*)d_out;

    const int smem = NS * STAGE_H * sizeof(__half);  // 4 * 36864 = 147456 B
    cudaFuncSetAttribute(gemm_mma_kernel,
                         cudaFuncAttributeMaxDynamicSharedMemorySize, smem);

    norm_kernel<<<1024, 256>>>(A, P);
    gemm_mma_kernel<<<dim3(NBLK, NBLK), 256, smem>>>();
    finalize_kernel<<<1, 256>>>(out);
}

// round 7
// speedup vs baseline: 7.9442x; 1.8809x over previous
#include <cuda_runtime.h>
#include <cuda_fp16.h>
#include <cstdint>
#include <math.h>

#define BDIM 4096
#define DDIM 1024
#define TM 128
#define TN 128
#define NBLK (BDIM / TM)      // 32 row/col blocks
#define NS 3                  // cp.async pipeline stages
#define KC 64                 // k-halfs per chunk
#define NCHUNK (DDIM / KC)    // 16
#define ROW_B 128             // bytes per smem row (no padding; XOR swizzle)
#define TILE_B (TM * ROW_B)   // 16384 B per tile
#define STAGE_B (2 * TILE_B)  // A + B per stage = 32768 B
#define SCALE 20.0f

// Scratch (allocation-free per harness rules)
__device__ __half g_a16[BDIM * DDIM];
__device__ __half g_p16[BDIM * DDIM];
__device__ float g_inv_a[BDIM];
__device__ float g_inv_p[BDIM];
__device__ float g_partial[BDIM * NBLK];
__device__ float g_diag[BDIM];
__device__ float g_rowloss[BDIM];

// ---------------------------------------------------------------- helpers
__device__ __forceinline__ uint32_t smem_u32(const void* p) {
    uint32_t a;
    asm("{ .reg .u64 t; cvta.to.shared.u64 t, %1; cvt.u32.u64 %0, t; }" : "=r"(a) : "l"(p));
    return a;
}
__device__ __forceinline__ void cp_async16(uint32_t dst, const void* src) {
    asm volatile("cp.async.cg.shared.global [%0], [%1], 16;" :: "r"(dst), "l"(src));
}
#define CP_COMMIT() asm volatile("cp.async.commit_group;" ::: "memory")
template <int N>
__device__ __forceinline__ void cp_wait() {
    asm volatile("cp.async.wait_group %0;" :: "n"(N) : "memory");
}
__device__ __forceinline__ void ldsm_x4(uint32_t* r, uint32_t addr) {
    asm volatile("ldmatrix.sync.aligned.m8n8.x4.shared.b16 {%0,%1,%2,%3}, [%4];"
                 : "=r"(r[0]), "=r"(r[1]), "=r"(r[2]), "=r"(r[3]) : "r"(addr));
}
// fp16 tensor-core MMA, fp32 accumulate: base-target PTX (sm_80+).
__device__ __forceinline__ void mma_f16(float* d, const uint32_t* a, const uint32_t* b) {
    asm volatile(
        "mma.sync.aligned.m16n8k16.row.col.f32.f16.f16.f32 "
        "{%0,%1,%2,%3}, {%4,%5,%6,%7}, {%8,%9}, {%0,%1,%2,%3};"
        : "+f"(d[0]), "+f"(d[1]), "+f"(d[2]), "+f"(d[3])
        : "r"(a[0]), "r"(a[1]), "r"(a[2]), "r"(a[3]), "r"(b[0]), "r"(b[1]));
}

// ---------------------------------------------------------------------------
// 1) Row inverse norms + fp32->fp16 conversion. One warp per row.
// ---------------------------------------------------------------------------
__global__ void norm_kernel(const float* __restrict__ A, const float* __restrict__ P) {
    const int row  = (blockIdx.x & 511) * 8 + (threadIdx.x >> 5);
    const bool isA = blockIdx.x < 512;
    const int lane = threadIdx.x & 31;
    const float* src = (isA ? A : P) + (size_t)row * DDIM;
    __half* dst = (isA ? g_a16 : g_p16) + (size_t)row * DDIM;

    float s = 0.0f;
    float4 v[8];
    #pragma unroll
    for (int i = 0; i < 8; i++) {
        v[i] = ((const float4*)src)[i * 32 + lane];
        s += v[i].x * v[i].x + v[i].y * v[i].y + v[i].z * v[i].z + v[i].w * v[i].w;
    }
    #pragma unroll
    for (int i = 0; i < 8; i++) {
        __half2 h0 = __floats2half2_rn(v[i].x, v[i].y);
        __half2 h1 = __floats2half2_rn(v[i].z, v[i].w);
        ((__half2*)dst)[(i * 32 + lane) * 2 + 0] = h0;
        ((__half2*)dst)[(i * 32 + lane) * 2 + 1] = h1;
    }
    #pragma unroll
    for (int o = 16; o > 0; o >>= 1) s += __shfl_xor_sync(0xffffffffu, s, o);
    if (lane == 0) {
        float inv = 1.0f / fmaxf(sqrtf(s), 1e-8f);
        if (isA) g_inv_a[row] = inv; else g_inv_p[row] = inv;
    }
}

// ---------------------------------------------------------------------------
// 2) fp16 mma.sync GEMM, 128x128 tile, XOR-swizzled smem (32KB/stage),
//    3 stages, 2 CTAs/SM. grid=(32,32), block=256.
// ---------------------------------------------------------------------------
__device__ __forceinline__ void load_chunk(char* smc, int c, int tid,
                                           const __half* Ab, const __half* Pb) {
    char* st = smc + (c % NS) * STAGE_B;
    const int k0 = c * KC;
    const int row = tid >> 3, q = tid & 7;   // 32 rows / pass, 8 16B-chunks per row
    #pragma unroll
    for (int j = 0; j < 4; j++) {
        int r = j * 32 + row;
        uint32_t dst = smem_u32(st + r * ROW_B + ((q ^ (r & 7)) << 4));
        cp_async16(dst, Ab + (size_t)r * DDIM + k0 + q * 8);
    }
    char* stb = st + TILE_B;
    #pragma unroll
    for (int j = 0; j < 4; j++) {
        int r = j * 32 + row;
        uint32_t dst = smem_u32(stb + r * ROW_B + ((q ^ (r & 7)) << 4));
        cp_async16(dst, Pb + (size_t)r * DDIM + k0 + q * 8);
    }
    CP_COMMIT();
}

__global__ __launch_bounds__(256, 2) void gemm_mma_kernel() {
    extern __shared__ char smc[];
    __shared__ float s_ia[TM];
    __shared__ float s_ip[TN];
    __shared__ float red[TM][2];

    const int tid  = threadIdx.x;
    const int lane = tid & 31;
    const int wid  = tid >> 5;
    const int wm   = (wid & 3) * 32;   // warp row offset
    const int wn   = (wid >> 2) * 64;  // warp col offset
    const int brow = blockIdx.y, bcol = blockIdx.x;

    const __half* Ab = g_a16 + (size_t)brow * TM * DDIM;
    const __half* Pb = g_p16 + (size_t)bcol * TN * DDIM;

    if (tid < 128)       s_ia[tid]       = SCALE * g_inv_a[brow * TM + tid];
    else                 s_ip[tid - 128] = g_inv_p[bcol * TN + (tid - 128)];

    #pragma unroll
    for (int c = 0; c < NS - 1; c++) load_chunk(smc, c, tid, Ab, Pb);

    float acc[2][8][4];
    #pragma unroll
    for (int mt = 0; mt < 2; mt++)
        #pragma unroll
        for (int nt = 0; nt < 8; nt++)
            #pragma unroll
            for (int r = 0; r < 4; r++) acc[mt][nt][r] = 0.0f;

    // ldmatrix lane decomposition
    const int lt = lane >> 3, lr = lane & 7;
    // Per-lane rows and base 16B-slot indices (swizzle applied per kk below)
    int rowA[2], rowB[4];
    #pragma unroll
    for (int mt = 0; mt < 2; mt++) rowA[mt] = wm + mt * 16 + (lt & 1) * 8 + lr;
    #pragma unroll
    for (int np = 0; np < 4; np++) rowB[np] = wn + np * 16 + (lt >> 1) * 8 + lr;
    const int idxA = lt >> 1;   // 0/1: 16B slot within k-chunk pair
    const int idxB = lt & 1;

    for (int c = 0; c < NCHUNK; c++) {
        if (c == NCHUNK - 1) cp_wait<0>(); else cp_wait<1>();
        __syncthreads();   // publish chunk c; closes WAR on stage (c+2)%NS (= chunk c-1's)
        if (c + NS - 1 < NCHUNK) load_chunk(smc, c + NS - 1, tid, Ab, Pb);

        const char* sA = smc + (c % NS) * STAGE_B;
        const char* sB = sA + TILE_B;

        #pragma unroll
        for (int kk = 0; kk < 4; kk++) {           // 4 x k16 covers KC=64
            uint32_t a[2][4], bf[16];
            #pragma unroll
            for (int mt = 0; mt < 2; mt++) {
                int slot = (idxA | (kk << 1)) ^ (rowA[mt] & 7);
                ldsm_x4(a[mt], smem_u32(sA + rowA[mt] * ROW_B + (slot << 4)));
            }
            #pragma unroll
            for (int np = 0; np < 4; np++) {
                int slot = (idxB | (kk << 1)) ^ (rowB[np] & 7);
                ldsm_x4(&bf[np * 4], smem_u32(sB + rowB[np] * ROW_B + (slot << 4)));
            }
            #pragma unroll
            for (int mt = 0; mt < 2; mt++)
                #pragma unroll
                for (int nt = 0; nt < 8; nt++)
                    mma_f16(acc[mt][nt], a[mt], &bf[nt * 2]);
        }
    }
    __syncthreads();

    // Epilogue: s = acc * (20*inv_a) * inv_p ; per-row sum of exp(s-20); diag.
    float rs[2][2] = {{0.0f, 0.0f}, {0.0f, 0.0f}};
    #pragma unroll
    for (int mt = 0; mt < 2; mt++) {
        #pragma unroll
        for (int h = 0; h < 2; h++) {
            const int rloc = wm + mt * 16 + (lane >> 2) + h * 8;
            const float ia = s_ia[rloc];
            const int grow = brow * TM + rloc;
            float acc_rs = 0.0f;
            #pragma unroll
            for (int nt = 0; nt < 8; nt++) {
                #pragma unroll
                for (int q = 0; q < 2; q++) {
                    const int cloc = wn + nt * 8 + (lane & 3) * 2 + q;
                    float s = acc[mt][nt][h * 2 + q] * ia * s_ip[cloc];
                    acc_rs += __expf(s - SCALE);
                    if (brow == bcol && rloc == cloc) g_diag[grow] = s;
                }
            }
            rs[mt][h] = acc_rs;
        }
    }
    #pragma unroll
    for (int mt = 0; mt < 2; mt++)
        #pragma unroll
        for (int h = 0; h < 2; h++) {
            rs[mt][h] += __shfl_xor_sync(0xffffffffu, rs[mt][h], 1);
            rs[mt][h] += __shfl_xor_sync(0xffffffffu, rs[mt][h], 2);
        }
    if ((lane & 3) == 0) {
        #pragma unroll
        for (int mt = 0; mt < 2; mt++)
            #pragma unroll
            for (int h = 0; h < 2; h++)
                red[wm + mt * 16 + (lane >> 2) + h * 8][wid >> 2] = rs[mt][h];
    }
    __syncthreads();
    if (tid < TM) {
        float t = red[tid][0] + red[tid][1];
        g_partial[(size_t)(brow * TM + tid) * NBLK + bcol] = t;
    }
}

// ---------------------------------------------------------------------------
// 3a) Per-row loss (parallel): rowloss = log(sum partials) + 20 - diag
// ---------------------------------------------------------------------------
__global__ void rowloss_kernel() {
    int r = blockIdx.x * 128 + threadIdx.x;
    float s = 0.0f;
    #pragma unroll
    for (int c = 0; c < NBLK; c++) s += g_partial[(size_t)r * NBLK + c];
    g_rowloss[r] = logf(s) + SCALE - g_diag[r];
}

// 3b) Deterministic mean of 4096 row losses
__global__ void finalize_kernel(float* __restrict__ out) {
    __shared__ float sred[256];
    float local = 0.0f;
    for (int r = threadIdx.x; r < BDIM; r += 256) local += g_rowloss[r];
    sred[threadIdx.x] = local;
    __syncthreads();
    #pragma unroll
    for (int o = 128; o > 0; o >>= 1) {
        if (threadIdx.x < o) sred[threadIdx.x] += sred[threadIdx.x + o];
        __syncthreads();
    }
    if (threadIdx.x == 0) out[0] = sred[0] * (1.0f / (float)BDIM);
}

// ---------------------------------------------------------------------------
extern "C" void kernel_launch(void* const* d_in, const int* in_sizes, int n_in,
                              void* d_out, int out_size) {
    const float* A = (const float*)d_in[0];   // anchor_emb  [4096, 1024]
    const float* P = (const float*)d_in[1];   // pos_negs_emb[4096, 1024]
    float* out = (float*)d_out;

    const int smem = NS * STAGE_B;            // 98304 B -> 2 CTAs/SM
    cudaFuncSetAttribute(gemm_mma_kernel,
                         cudaFuncAttributeMaxDynamicSharedMemorySize, smem);

    norm_kernel<<<1024, 256>>>(A, P);
    gemm_mma_kernel<<<dim3(NBLK, NBLK), 256, smem>>>();
    rowloss_kernel<<<BDIM / 128, 128>>>();
    finalize_kernel<<<1, 256>>>(out);
}

// round 8
// speedup vs baseline: 8.1181x; 1.0219x over previous
#include <cuda_runtime.h>
#include <cuda_fp16.h>
#include <cstdint>
#include <math.h>

#define BDIM 4096
#define DDIM 1024
#define TM 128
#define TN 128
#define NBLK (BDIM / TM)      // 32 row/col blocks
#define NS 3                  // cp.async pipeline stages
#define KC 64                 // k-halfs per chunk
#define NCHUNK (DDIM / KC)    // 16
#define ROW_B 128             // bytes per smem row (no padding; XOR swizzle)
#define TILE_B (TM * ROW_B)   // 16384 B per tile
#define STAGE_B (2 * TILE_B)  // A + B per stage = 32768 B
#define SCALE 20.0f

// Scratch (allocation-free per harness rules)
__device__ __half g_a16[BDIM * DDIM];
__device__ __half g_p16[BDIM * DDIM];
__device__ float g_inv_a[BDIM];
__device__ float g_inv_p[BDIM];
__device__ float g_partial[BDIM * NBLK];
__device__ float g_diag[BDIM];
__device__ float g_blocksum[NBLK];

// ---------------------------------------------------------------- helpers
__device__ __forceinline__ uint32_t smem_u32(const void* p) {
    uint32_t a;
    asm("{ .reg .u64 t; cvta.to.shared.u64 t, %1; cvt.u32.u64 %0, t; }" : "=r"(a) : "l"(p));
    return a;
}
__device__ __forceinline__ void cp_async16(uint32_t dst, const void* src) {
    asm volatile("cp.async.cg.shared.global [%0], [%1], 16;" :: "r"(dst), "l"(src));
}
#define CP_COMMIT() asm volatile("cp.async.commit_group;" ::: "memory")
template <int N>
__device__ __forceinline__ void cp_wait() {
    asm volatile("cp.async.wait_group %0;" :: "n"(N) : "memory");
}
__device__ __forceinline__ void ldsm_x4(uint32_t* r, uint32_t addr) {
    asm volatile("ldmatrix.sync.aligned.m8n8.x4.shared.b16 {%0,%1,%2,%3}, [%4];"
                 : "=r"(r[0]), "=r"(r[1]), "=r"(r[2]), "=r"(r[3]) : "r"(addr));
}
// fp16 tensor-core MMA, fp32 accumulate: base-target PTX (sm_80+).
__device__ __forceinline__ void mma_f16(float* d, const uint32_t* a, const uint32_t* b) {
    asm volatile(
        "mma.sync.aligned.m16n8k16.row.col.f32.f16.f16.f32 "
        "{%0,%1,%2,%3}, {%4,%5,%6,%7}, {%8,%9}, {%0,%1,%2,%3};"
        : "+f"(d[0]), "+f"(d[1]), "+f"(d[2]), "+f"(d[3])
        : "r"(a[0]), "r"(a[1]), "r"(a[2]), "r"(a[3]), "r"(b[0]), "r"(b[1]));
}

// ---------------------------------------------------------------------------
// 1) Row inverse norms + fp32->fp16 conversion. One warp per row.
// ---------------------------------------------------------------------------
__global__ void norm_kernel(const float* __restrict__ A, const float* __restrict__ P) {
    const int row  = (blockIdx.x & 511) * 8 + (threadIdx.x >> 5);
    const bool isA = blockIdx.x < 512;
    const int lane = threadIdx.x & 31;
    const float* src = (isA ? A : P) + (size_t)row * DDIM;
    __half* dst = (isA ? g_a16 : g_p16) + (size_t)row * DDIM;

    float s = 0.0f;
    float4 v[8];
    #pragma unroll
    for (int i = 0; i < 8; i++) {
        v[i] = ((const float4*)src)[i * 32 + lane];
        s += v[i].x * v[i].x + v[i].y * v[i].y + v[i].z * v[i].z + v[i].w * v[i].w;
    }
    #pragma unroll
    for (int i = 0; i < 8; i++) {
        __half2 h0 = __floats2half2_rn(v[i].x, v[i].y);
        __half2 h1 = __floats2half2_rn(v[i].z, v[i].w);
        ((__half2*)dst)[(i * 32 + lane) * 2 + 0] = h0;
        ((__half2*)dst)[(i * 32 + lane) * 2 + 1] = h1;
    }
    #pragma unroll
    for (int o = 16; o > 0; o >>= 1) s += __shfl_xor_sync(0xffffffffu, s, o);
    if (lane == 0) {
        float inv = 1.0f / fmaxf(sqrtf(s), 1e-8f);
        if (isA) g_inv_a[row] = inv; else g_inv_p[row] = inv;
    }
}

// ---------------------------------------------------------------------------
// 2) fp16 mma.sync GEMM, 128x128 tile, XOR-swizzled smem (32KB/stage),
//    3 stages, 2 CTAs/SM. grid=(32,32), block=256.
// ---------------------------------------------------------------------------
__device__ __forceinline__ void load_chunk(char* smc, int c, int tid,
                                           const __half* Ab, const __half* Pb) {
    char* st = smc + (c % NS) * STAGE_B;
    const int k0 = c * KC;
    const int row = tid >> 3, q = tid & 7;   // 32 rows / pass, 8 16B-chunks per row
    #pragma unroll
    for (int j = 0; j < 4; j++) {
        int r = j * 32 + row;
        uint32_t dst = smem_u32(st + r * ROW_B + ((q ^ (r & 7)) << 4));
        cp_async16(dst, Ab + (size_t)r * DDIM + k0 + q * 8);
    }
    char* stb = st + TILE_B;
    #pragma unroll
    for (int j = 0; j < 4; j++) {
        int r = j * 32 + row;
        uint32_t dst = smem_u32(stb + r * ROW_B + ((q ^ (r & 7)) << 4));
        cp_async16(dst, Pb + (size_t)r * DDIM + k0 + q * 8);
    }
    CP_COMMIT();
}

__global__ __launch_bounds__(256, 2) void gemm_mma_kernel() {
    extern __shared__ char smc[];
    __shared__ float s_ia[TM];
    __shared__ float s_ip[TN];
    __shared__ float red[TM][2];

    const int tid  = threadIdx.x;
    const int lane = tid & 31;
    const int wid  = tid >> 5;
    const int wm   = (wid & 3) * 32;   // warp row offset
    const int wn   = (wid >> 2) * 64;  // warp col offset
    const int brow = blockIdx.y, bcol = blockIdx.x;

    const __half* Ab = g_a16 + (size_t)brow * TM * DDIM;
    const __half* Pb = g_p16 + (size_t)bcol * TN * DDIM;

    if (tid < 128)       s_ia[tid]       = SCALE * g_inv_a[brow * TM + tid];
    else                 s_ip[tid - 128] = g_inv_p[bcol * TN + (tid - 128)];

    #pragma unroll
    for (int c = 0; c < NS - 1; c++) load_chunk(smc, c, tid, Ab, Pb);

    float acc[2][8][4];
    #pragma unroll
    for (int mt = 0; mt < 2; mt++)
        #pragma unroll
        for (int nt = 0; nt < 8; nt++)
            #pragma unroll
            for (int r = 0; r < 4; r++) acc[mt][nt][r] = 0.0f;

    // ldmatrix lane decomposition
    const int lt = lane >> 3, lr = lane & 7;
    int rowA[2], rowB[4];
    #pragma unroll
    for (int mt = 0; mt < 2; mt++) rowA[mt] = wm + mt * 16 + (lt & 1) * 8 + lr;
    #pragma unroll
    for (int np = 0; np < 4; np++) rowB[np] = wn + np * 16 + (lt >> 1) * 8 + lr;
    const int idxA = lt >> 1;
    const int idxB = lt & 1;

    for (int c = 0; c < NCHUNK; c++) {
        if (c == NCHUNK - 1) cp_wait<0>(); else cp_wait<1>();
        __syncthreads();   // publish chunk c; closes WAR on stage (c+2)%NS
        if (c + NS - 1 < NCHUNK) load_chunk(smc, c + NS - 1, tid, Ab, Pb);

        const char* sA = smc + (c % NS) * STAGE_B;
        const char* sB = sA + TILE_B;

        #pragma unroll
        for (int kk = 0; kk < 4; kk++) {           // 4 x k16 covers KC=64
            uint32_t a[2][4], bf[16];
            #pragma unroll
            for (int mt = 0; mt < 2; mt++) {
                int slot = (idxA | (kk << 1)) ^ (rowA[mt] & 7);
                ldsm_x4(a[mt], smem_u32(sA + rowA[mt] * ROW_B + (slot << 4)));
            }
            #pragma unroll
            for (int np = 0; np < 4; np++) {
                int slot = (idxB | (kk << 1)) ^ (rowB[np] & 7);
                ldsm_x4(&bf[np * 4], smem_u32(sB + rowB[np] * ROW_B + (slot << 4)));
            }
            #pragma unroll
            for (int mt = 0; mt < 2; mt++)
                #pragma unroll
                for (int nt = 0; nt < 8; nt++)
                    mma_f16(acc[mt][nt], a[mt], &bf[nt * 2]);
        }
    }
    __syncthreads();

    // Epilogue: s = acc * (20*inv_a) * inv_p ; per-row sum of exp(s-20); diag.
    float rs[2][2] = {{0.0f, 0.0f}, {0.0f, 0.0f}};
    #pragma unroll
    for (int mt = 0; mt < 2; mt++) {
        #pragma unroll
        for (int h = 0; h < 2; h++) {
            const int rloc = wm + mt * 16 + (lane >> 2) + h * 8;
            const float ia = s_ia[rloc];
            const int grow = brow * TM + rloc;
            float acc_rs = 0.0f;
            #pragma unroll
            for (int nt = 0; nt < 8; nt++) {
                const int cbase = wn + nt * 8 + (lane & 3) * 2;
                const float ip0 = s_ip[cbase], ip1 = s_ip[cbase + 1];
                float s0 = acc[mt][nt][h * 2 + 0] * ia * ip0;
                float s1 = acc[mt][nt][h * 2 + 1] * ia * ip1;
                acc_rs += __expf(s0 - SCALE) + __expf(s1 - SCALE);
                if (brow == bcol) {
                    if (rloc == cbase)     g_diag[grow] = s0;
                    if (rloc == cbase + 1) g_diag[grow] = s1;
                }
            }
            rs[mt][h] = acc_rs;
        }
    }
    #pragma unroll
    for (int mt = 0; mt < 2; mt++)
        #pragma unroll
        for (int h = 0; h < 2; h++) {
            rs[mt][h] += __shfl_xor_sync(0xffffffffu, rs[mt][h], 1);
            rs[mt][h] += __shfl_xor_sync(0xffffffffu, rs[mt][h], 2);
        }
    if ((lane & 3) == 0) {
        #pragma unroll
        for (int mt = 0; mt < 2; mt++)
            #pragma unroll
            for (int h = 0; h < 2; h++)
                red[wm + mt * 16 + (lane >> 2) + h * 8][wid >> 2] = rs[mt][h];
    }
    __syncthreads();
    if (tid < TM) {
        float t = red[tid][0] + red[tid][1];
        g_partial[(size_t)(brow * TM + tid) * NBLK + bcol] = t;
    }
}

// ---------------------------------------------------------------------------
// 3a) Per-row loss + per-block partial mean: 32 blocks x 128 threads.
//     Each block reduces its 128 row losses into g_blocksum[blockIdx].
// ---------------------------------------------------------------------------
__global__ void rowloss_kernel() {
    __shared__ float ws[4];
    const int r = blockIdx.x * 128 + threadIdx.x;
    float s = 0.0f;
    #pragma unroll
    for (int c = 0; c < NBLK; c++) s += g_partial[(size_t)r * NBLK + c];
    float rl = logf(s) + SCALE - g_diag[r];
    #pragma unroll
    for (int o = 16; o > 0; o >>= 1) rl += __shfl_xor_sync(0xffffffffu, rl, o);
    if ((threadIdx.x & 31) == 0) ws[threadIdx.x >> 5] = rl;
    __syncthreads();
    if (threadIdx.x == 0)
        g_blocksum[blockIdx.x] = ws[0] + ws[1] + ws[2] + ws[3];
}

// 3b) Deterministic mean: one warp sums 32 block sums.
__global__ void finalize_kernel(float* __restrict__ out) {
    float v = g_blocksum[threadIdx.x];   // 32 threads
    #pragma unroll
    for (int o = 16; o > 0; o >>= 1) v += __shfl_xor_sync(0xffffffffu, v, o);
    if (threadIdx.x == 0) out[0] = v * (1.0f / (float)BDIM);
}

// ---------------------------------------------------------------------------
extern "C" void kernel_launch(void* const* d_in, const int* in_sizes, int n_in,
                              void* d_out, int out_size) {
    const float* A = (const float*)d_in[0];   // anchor_emb  [4096, 1024]
    const float* P = (const float*)d_in[1];   // pos_negs_emb[4096, 1024]
    float* out = (float*)d_out;

    const int smem = NS * STAGE_B;            // 98304 B -> 2 CTAs/SM
    cudaFuncSetAttribute(gemm_mma_kernel,
                         cudaFuncAttributeMaxDynamicSharedMemorySize, smem);

    norm_kernel<<<1024, 256>>>(A, P);
    gemm_mma_kernel<<<dim3(NBLK, NBLK), 256, smem>>>();
    rowloss_kernel<<<NBLK, 128>>>();
    finalize_kernel<<<1, 32>>>(out);
}

// round 10
// speedup vs baseline: 8.1622x; 1.0054x over previous
#include <cuda_runtime.h>
#include <cuda_fp16.h>
#include <cstdint>
#include <math.h>

#define BDIM 4096
#define DDIM 1024
#define TM 128
#define TN 128
#define NBLK (BDIM / TM)      // 32 row/col blocks
#define NS 3                  // cp.async pipeline stages
#define KC 64                 // k-halfs per chunk
#define NCHUNK (DDIM / KC)    // 16
#define ROW_B 128             // bytes per smem row (no padding; XOR swizzle)
#define TILE_B (TM * ROW_B)   // 16384 B per tile
#define STAGE_B (2 * TILE_B)  // A + B per stage = 32768 B
#define SCALE 20.0f

// Scratch (allocation-free per harness rules)
__device__ __half g_a16[BDIM * DDIM];
__device__ __half g_p16[BDIM * DDIM];
__device__ float g_inv_a[BDIM];
__device__ float g_inv_p[BDIM];
__device__ float g_partial[BDIM * NBLK];
__device__ float g_diag[BDIM];
__device__ float g_blocksum[NBLK];
__device__ int g_count;               // zero-init; reset to 0 after each use

// ---------------------------------------------------------------- helpers
__device__ __forceinline__ uint32_t smem_u32(const void* p) {
    uint32_t a;
    asm("{ .reg .u64 t; cvta.to.shared.u64 t, %1; cvt.u32.u64 %0, t; }" : "=r"(a) : "l"(p));
    return a;
}
__device__ __forceinline__ uint32_t h2_bits(__half2 h) {
    return *reinterpret_cast<const uint32_t*>(&h);
}
__device__ __forceinline__ void cp_async16(uint32_t dst, const void* src) {
    asm volatile("cp.async.cg.shared.global [%0], [%1], 16;" :: "r"(dst), "l"(src));
}
#define CP_COMMIT() asm volatile("cp.async.commit_group;" ::: "memory")
template <int N>
__device__ __forceinline__ void cp_wait() {
    asm volatile("cp.async.wait_group %0;" :: "n"(N) : "memory");
}
__device__ __forceinline__ void ldsm_x4(uint32_t* r, uint32_t addr) {
    asm volatile("ldmatrix.sync.aligned.m8n8.x4.shared.b16 {%0,%1,%2,%3}, [%4];"
                 : "=r"(r[0]), "=r"(r[1]), "=r"(r[2]), "=r"(r[3]) : "r"(addr));
}
// fp16 tensor-core MMA, fp32 accumulate: base-target PTX (sm_80+).
__device__ __forceinline__ void mma_f16(float* d, const uint32_t* a, const uint32_t* b) {
    asm volatile(
        "mma.sync.aligned.m16n8k16.row.col.f32.f16.f16.f32 "
        "{%0,%1,%2,%3}, {%4,%5,%6,%7}, {%8,%9}, {%0,%1,%2,%3};"
        : "+f"(d[0]), "+f"(d[1]), "+f"(d[2]), "+f"(d[3])
        : "r"(a[0]), "r"(a[1]), "r"(a[2]), "r"(a[3]), "r"(b[0]), "r"(b[1]));
}

// ---------------------------------------------------------------------------
// 1) Row inverse norms + fp32->fp16 conversion. One warp per row.
//    Paired float4 loads -> single 16B packed-half store per lane per pass.
// ---------------------------------------------------------------------------
__global__ void norm_kernel(const float* __restrict__ A, const float* __restrict__ P) {
    const int row  = (blockIdx.x & 511) * 8 + (threadIdx.x >> 5);
    const bool isA = blockIdx.x < 512;
    const int lane = threadIdx.x & 31;
    const float4* src = (const float4*)((isA ? A : P) + (size_t)row * DDIM);
    uint4* dst = (uint4*)((isA ? g_a16 : g_p16) + (size_t)row * DDIM);

    float s = 0.0f;
    float4 v0[4], v1[4];
    #pragma unroll
    for (int i = 0; i < 4; i++) {
        v0[i] = src[i * 64 + lane * 2];
        v1[i] = src[i * 64 + lane * 2 + 1];
        s += v0[i].x * v0[i].x + v0[i].y * v0[i].y + v0[i].z * v0[i].z + v0[i].w * v0[i].w;
        s += v1[i].x * v1[i].x + v1[i].y * v1[i].y + v1[i].z * v1[i].z + v1[i].w * v1[i].w;
    }
    #pragma unroll
    for (int i = 0; i < 4; i++) {
        uint4 pk;
        pk.x = h2_bits(__floats2half2_rn(v0[i].x, v0[i].y));
        pk.y = h2_bits(__floats2half2_rn(v0[i].z, v0[i].w));
        pk.z = h2_bits(__floats2half2_rn(v1[i].x, v1[i].y));
        pk.w = h2_bits(__floats2half2_rn(v1[i].z, v1[i].w));
        dst[i * 32 + lane] = pk;
    }
    #pragma unroll
    for (int o = 16; o > 0; o >>= 1) s += __shfl_xor_sync(0xffffffffu, s, o);
    if (lane == 0) {
        float inv = 1.0f / fmaxf(sqrtf(s), 1e-8f);
        if (isA) g_inv_a[row] = inv; else g_inv_p[row] = inv;
    }
}

// ---------------------------------------------------------------------------
// 2) fp16 mma.sync GEMM, 128x128 tile, XOR-swizzled smem (32KB/stage),
//    3 stages, 2 CTAs/SM. grid=(32,32), block=256.  (unchanged from R7/R8)
// ---------------------------------------------------------------------------
__device__ __forceinline__ void load_chunk(char* smc, int c, int tid,
                                           const __half* Ab, const __half* Pb) {
    char* st = smc + (c % NS) * STAGE_B;
    const int k0 = c * KC;
    const int row = tid >> 3, q = tid & 7;
    #pragma unroll
    for (int j = 0; j < 4; j++) {
        int r = j * 32 + row;
        uint32_t dst = smem_u32(st + r * ROW_B + ((q ^ (r & 7)) << 4));
        cp_async16(dst, Ab + (size_t)r * DDIM + k0 + q * 8);
    }
    char* stb = st + TILE_B;
    #pragma unroll
    for (int j = 0; j < 4; j++) {
        int r = j * 32 + row;
        uint32_t dst = smem_u32(stb + r * ROW_B + ((q ^ (r & 7)) << 4));
        cp_async16(dst, Pb + (size_t)r * DDIM + k0 + q * 8);
    }
    CP_COMMIT();
}

__global__ __launch_bounds__(256, 2) void gemm_mma_kernel() {
    extern __shared__ char smc[];
    __shared__ float s_ia[TM];
    __shared__ float s_ip[TN];
    __shared__ float red[TM][2];

    const int tid  = threadIdx.x;
    const int lane = tid & 31;
    const int wid  = tid >> 5;
    const int wm   = (wid & 3) * 32;
    const int wn   = (wid >> 2) * 64;
    const int brow = blockIdx.y, bcol = blockIdx.x;

    const __half* Ab = g_a16 + (size_t)brow * TM * DDIM;
    const __half* Pb = g_p16 + (size_t)bcol * TN * DDIM;

    if (tid < 128)       s_ia[tid]       = SCALE * g_inv_a[brow * TM + tid];
    else                 s_ip[tid - 128] = g_inv_p[bcol * TN + (tid - 128)];

    #pragma unroll
    for (int c = 0; c < NS - 1; c++) load_chunk(smc, c, tid, Ab, Pb);

    float acc[2][8][4];
    #pragma unroll
    for (int mt = 0; mt < 2; mt++)
        #pragma unroll
        for (int nt = 0; nt < 8; nt++)
            #pragma unroll
            for (int r = 0; r < 4; r++) acc[mt][nt][r] = 0.0f;

    const int lt = lane >> 3, lr = lane & 7;
    int rowA[2], rowB[4];
    #pragma unroll
    for (int mt = 0; mt < 2; mt++) rowA[mt] = wm + mt * 16 + (lt & 1) * 8 + lr;
    #pragma unroll
    for (int np = 0; np < 4; np++) rowB[np] = wn + np * 16 + (lt >> 1) * 8 + lr;
    const int idxA = lt >> 1;
    const int idxB = lt & 1;

    for (int c = 0; c < NCHUNK; c++) {
        if (c == NCHUNK - 1) cp_wait<0>(); else cp_wait<1>();
        __syncthreads();
        if (c + NS - 1 < NCHUNK) load_chunk(smc, c + NS - 1, tid, Ab, Pb);

        const char* sA = smc + (c % NS) * STAGE_B;
        const char* sB = sA + TILE_B;

        #pragma unroll
        for (int kk = 0; kk < 4; kk++) {
            uint32_t a[2][4], bf[16];
            #pragma unroll
            for (int mt = 0; mt < 2; mt++) {
                int slot = (idxA | (kk << 1)) ^ (rowA[mt] & 7);
                ldsm_x4(a[mt], smem_u32(sA + rowA[mt] * ROW_B + (slot << 4)));
            }
            #pragma unroll
            for (int np = 0; np < 4; np++) {
                int slot = (idxB | (kk << 1)) ^ (rowB[np] & 7);
                ldsm_x4(&bf[np * 4], smem_u32(sB + rowB[np] * ROW_B + (slot << 4)));
            }
            #pragma unroll
            for (int mt = 0; mt < 2; mt++)
                #pragma unroll
                for (int nt = 0; nt < 8; nt++)
                    mma_f16(acc[mt][nt], a[mt], &bf[nt * 2]);
        }
    }
    __syncthreads();

    float rs[2][2] = {{0.0f, 0.0f}, {0.0f, 0.0f}};
    #pragma unroll
    for (int mt = 0; mt < 2; mt++) {
        #pragma unroll
        for (int h = 0; h < 2; h++) {
            const int rloc = wm + mt * 16 + (lane >> 2) + h * 8;
            const float ia = s_ia[rloc];
            const int grow = brow * TM + rloc;
            float acc_rs = 0.0f;
            #pragma unroll
            for (int nt = 0; nt < 8; nt++) {
                const int cbase = wn + nt * 8 + (lane & 3) * 2;
                const float ip0 = s_ip[cbase], ip1 = s_ip[cbase + 1];
                float s0 = acc[mt][nt][h * 2 + 0] * ia * ip0;
                float s1 = acc[mt][nt][h * 2 + 1] * ia * ip1;
                acc_rs += __expf(s0 - SCALE) + __expf(s1 - SCALE);
                if (brow == bcol) {
                    if (rloc == cbase)     g_diag[grow] = s0;
                    if (rloc == cbase + 1) g_diag[grow] = s1;
                }
            }
            rs[mt][h] = acc_rs;
        }
    }
    #pragma unroll
    for (int mt = 0; mt < 2; mt++)
        #pragma unroll
        for (int h = 0; h < 2; h++) {
            rs[mt][h] += __shfl_xor_sync(0xffffffffu, rs[mt][h], 1);
            rs[mt][h] += __shfl_xor_sync(0xffffffffu, rs[mt][h], 2);
        }
    if ((lane & 3) == 0) {
        #pragma unroll
        for (int mt = 0; mt < 2; mt++)
            #pragma unroll
            for (int h = 0; h < 2; h++)
                red[wm + mt * 16 + (lane >> 2) + h * 8][wid >> 2] = rs[mt][h];
    }
    __syncthreads();
    if (tid < TM) {
        float t = red[tid][0] + red[tid][1];
        g_partial[(size_t)(brow * TM + tid) * NBLK + bcol] = t;
    }
}

// ---------------------------------------------------------------------------
// 3) Fused tail: per-row loss, per-block sum, last block finalizes.
//    Deterministic: final 32-value sum is done by ONE block in fixed order.
//    g_count is reset to 0 for the next graph replay.
// ---------------------------------------------------------------------------
__global__ void rowloss_kernel(float* __restrict__ out) {
    __shared__ float ws[4];
    const int r = blockIdx.x * 128 + threadIdx.x;
    float s = 0.0f;
    #pragma unroll
    for (int c = 0; c < NBLK; c++) s += g_partial[(size_t)r * NBLK + c];
    float rl = logf(s) + SCALE - g_diag[r];
    #pragma unroll
    for (int o = 16; o > 0; o >>= 1) rl += __shfl_xor_sync(0xffffffffu, rl, o);
    if ((threadIdx.x & 31) == 0) ws[threadIdx.x >> 5] = rl;
    __syncthreads();
    if (threadIdx.x == 0) {
        g_blocksum[blockIdx.x] = ws[0] + ws[1] + ws[2] + ws[3];
        __threadfence();
        int v = atomicAdd(&g_count, 1);
        if (v == NBLK - 1) {             // last block: all blocksums visible
            float t = 0.0f;
            #pragma unroll
            for (int i = 0; i < NBLK; i++) t += g_blocksum[i];
            out[0] = t * (1.0f / (float)BDIM);
            g_count = 0;                 // reset for next replay
        }
    }
}

// ---------------------------------------------------------------------------
extern "C" void kernel_launch(void* const* d_in, const int* in_sizes, int n_in,
                              void* d_out, int out_size) {
    const float* A = (const float*)d_in[0];   // anchor_emb  [4096, 1024]
    const float* P = (const float*)d_in[1];   // pos_negs_emb[4096, 1024]
    float* out = (float*)d_out;

    const int smem = NS * STAGE_B;            // 98304 B -> 2 CTAs/SM
    cudaFuncSetAttribute(gemm_mma_kernel,
                         cudaFuncAttributeMaxDynamicSharedMemorySize, smem);

    norm_kernel<<<1024, 256>>>(A, P);
    gemm_mma_kernel<<<dim3(NBLK, NBLK), 256, smem>>>();
    rowloss_kernel<<<NBLK, 128>>>(out);
}